// round 7
// baseline (speedup 1.0000x reference)
#include <cuda_runtime.h>

#define NA 200000
#define NDG 50000
#define NB 8192
#define EPSBN 1e-5f
#define TPD 391           // row tiles per degree = ceil(50000/128)
#define FPB 1563          // fp blocks = ceil(200000/128)
#define ARS 132           // padded smem row stride (floats)

typedef unsigned long long u64;

__device__ __forceinline__ u64 pack2(float lo, float hi) {
    u64 r; asm("mov.b64 %0, {%1, %2};" : "=l"(r) : "f"(lo), "f"(hi)); return r;
}
__device__ __forceinline__ void unpack2(u64 v, float& lo, float& hi) {
    asm("mov.b64 {%0, %1}, %2;" : "=f"(lo), "=f"(hi) : "l"(v));
}
__device__ __forceinline__ u64 ffma2(u64 a, u64 b, u64 c) {
    u64 d; asm("fma.rn.f32x2 %0, %1, %2, %3;" : "=l"(d) : "l"(a), "l"(b), "l"(c)); return d;
}

// ---------------- scratch ----------------
__device__ float g_G[(size_t)NA * 272];
__device__ float g_H[(size_t)NA * 128];
__device__ float g_X[(size_t)NA * 128];
__device__ float g_stats[512];
__device__ float g_sc[256];
__device__ float g_sh[256];

__global__ void zero_stats_kernel() {
    int i = threadIdx.x;
    if (i < 512) g_stats[i] = 0.f;
}

__global__ void prep_stats_kernel(int statsOff, int scOff) {
    int j = threadIdx.x;
    float mean = g_stats[statsOff + j] * (1.f / NA);
    float var  = g_stats[statsOff + 128 + j] * (1.f / NA) - mean * mean;
    float r = rsqrtf(var + EPSBN);
    g_sc[scOff + j] = r;
    g_sh[scOff + j] = -mean * r;
}

// ---------------- gather (BN+relu optionally fused on atom features) ----------------
template <int KIN, bool NORM>
__global__ void gather_kernel(const float* __restrict__ Hin,
                              const float* __restrict__ bond,
                              const int* __restrict__ a1, const int* __restrict__ a2,
                              const int* __restrict__ a3, const int* __restrict__ a4,
                              const int* __restrict__ b1, const int* __restrict__ b2,
                              const int* __restrict__ b3, const int* __restrict__ b4,
                              int scOff) {
    constexpr int CK  = 2 * KIN + 16;
    constexpr int CK4 = CK / 4;
    long long idx = (long long)blockIdx.x * blockDim.x + threadIdx.x;
    if (idx >= (long long)NA * CK4) return;
    int row = (int)(idx / CK4);
    int c4  = (int)(idx - (long long)row * CK4);
    int d   = row / NDG;
    int r   = row - d * NDG;
    int deg = d + 1;
    const int* aidx; const int* bidx;
    if (d == 0)      { aidx = a1; bidx = b1; }
    else if (d == 1) { aidx = a2; bidx = b2; }
    else if (d == 2) { aidx = a3; bidx = b3; }
    else             { aidx = a4; bidx = b4; }
    int c = c4 * 4;
    float4 out;
    if (c < KIN) {
        float4 v = *(const float4*)(Hin + (size_t)row * KIN + c);
        if (NORM) {
            float4 sc4 = *(const float4*)&g_sc[scOff + c];
            float4 sh4 = *(const float4*)&g_sh[scOff + c];
            v.x = fmaxf(0.f, fmaf(v.x, sc4.x, sh4.x));
            v.y = fmaxf(0.f, fmaf(v.y, sc4.y, sh4.y));
            v.z = fmaxf(0.f, fmaf(v.z, sc4.z, sh4.z));
            v.w = fmaxf(0.f, fmaf(v.w, sc4.w, sh4.w));
        }
        out = v;
    } else if (c < 2 * KIN) {
        int cc = c - KIN;
        float4 sc4, sh4;
        if (NORM) {
            sc4 = *(const float4*)&g_sc[scOff + cc];
            sh4 = *(const float4*)&g_sh[scOff + cc];
        }
        float4 s = make_float4(0.f, 0.f, 0.f, 0.f);
        #pragma unroll 4
        for (int t = 0; t < deg; t++) {
            int nb = aidx[r * deg + t];
            float4 v = *(const float4*)(Hin + (size_t)nb * KIN + cc);
            if (NORM) {
                v.x = fmaxf(0.f, fmaf(v.x, sc4.x, sh4.x));
                v.y = fmaxf(0.f, fmaf(v.y, sc4.y, sh4.y));
                v.z = fmaxf(0.f, fmaf(v.z, sc4.z, sh4.z));
                v.w = fmaxf(0.f, fmaf(v.w, sc4.w, sh4.w));
            }
            s.x += v.x; s.y += v.y; s.z += v.z; s.w += v.w;
        }
        out = s;
    } else {
        int cc = c - 2 * KIN;
        float4 s = make_float4(0.f, 0.f, 0.f, 0.f);
        #pragma unroll 4
        for (int t = 0; t < deg; t++) {
            int nb = bidx[r * deg + t];
            float4 v = *(const float4*)(bond + (size_t)nb * 16 + cc);
            s.x += v.x; s.y += v.y; s.z += v.z; s.w += v.w;
        }
        out = s;
    }
    *(float4*)(g_G + (size_t)row * CK + c) = out;
}

// ---------------- GEMM core: 256 threads, thread tile 16 rows x 4 cols ----------------
// As[k][row] k-major (warp-uniform row group -> broadcast LDS), Ws[k][col]
__device__ __forceinline__ void sts_chunk(float* As, float* Ws, int tid,
                                          const float4 a[2], const float4 w[2]) {
    int rl = tid & 127, kk = (tid >> 7) * 8;
    #pragma unroll
    for (int q = 0; q < 2; q++) {
        As[(kk + q * 4 + 0) * ARS + rl] = a[q].x;
        As[(kk + q * 4 + 1) * ARS + rl] = a[q].y;
        As[(kk + q * 4 + 2) * ARS + rl] = a[q].z;
        As[(kk + q * 4 + 3) * ARS + rl] = a[q].w;
        int f = tid + q * 256;
        *(float4*)&Ws[(f >> 5) * ARS + (f & 31) * 4] = w[q];
    }
}

__device__ __forceinline__ void compute_chunk(const float* As, const float* Ws,
                                              int tx, int ty, u64 acc[8][4]) {
    #pragma unroll 4
    for (int k = 0; k < 16; k++) {
        float4 w0 = *(const float4*)&Ws[k * ARS + tx * 4];
        u64 wd[4];
        wd[0] = pack2(w0.x, w0.x); wd[1] = pack2(w0.y, w0.y);
        wd[2] = pack2(w0.z, w0.z); wd[3] = pack2(w0.w, w0.w);
        ulonglong2 A0 = *(const ulonglong2*)&As[k * ARS + ty * 16];
        ulonglong2 A1 = *(const ulonglong2*)&As[k * ARS + ty * 16 + 4];
        ulonglong2 A2 = *(const ulonglong2*)&As[k * ARS + ty * 16 + 8];
        ulonglong2 A3 = *(const ulonglong2*)&As[k * ARS + ty * 16 + 12];
        u64 ap[8] = {A0.x, A0.y, A1.x, A1.y, A2.x, A2.y, A3.x, A3.y};
        #pragma unroll
        for (int rp = 0; rp < 8; rp++) {
            #pragma unroll
            for (int j = 0; j < 4; j++)
                acc[rp][j] = ffma2(ap[rp], wd[j], acc[rp][j]);
        }
    }
}

// ---------------- conv GEMM ----------------
template <int KIN>
__global__ __launch_bounds__(256, 2)
void conv_kernel(const float* __restrict__ selfW,
                 const float* __restrict__ dW1, const float* __restrict__ dW2,
                 const float* __restrict__ dW3, const float* __restrict__ dW4,
                 const float* __restrict__ bias,
                 float* __restrict__ Xout, int statsOff) {
    constexpr int CK  = 2 * KIN + 16;
    constexpr int NCH = CK / 16;
    __shared__ alignas(16) float As2[2][16 * ARS];
    __shared__ alignas(16) float Ws2[2][16 * ARS];

    int tid = threadIdx.x;
    int tx = tid & 31, ty = tid >> 5;          // cols tx*4.., rows ty*16..
    int d    = blockIdx.x / TPD;
    int tile = blockIdx.x - d * TPD;
    int rowbase = d * NDG + tile * 128;
    int rowend  = min((d + 1) * NDG, rowbase + 128);
    const float* dW = (d == 0) ? dW1 : (d == 1) ? dW2 : (d == 2) ? dW3 : dW4;

    int rl = tid & 127, kk = (tid >> 7) * 8;
    int rg = rowbase + rl;
    bool rvalid = rg < rowend;
    const float* Grow = g_G + (size_t)rg * CK + kk;

    float4 bcol = *(const float4*)&bias[tx * 4];

    float4 a[2], w[2];
    #pragma unroll
    for (int q = 0; q < 2; q++) {
        a[q] = rvalid ? *(const float4*)(Grow + 4 * q) : make_float4(0,0,0,0);
        w[q] = ((const float4*)selfW)[tid + q * 256];
    }
    sts_chunk(As2[0], Ws2[0], tid, a, w);
    __syncthreads();

    u64 acc[8][4];
    #pragma unroll
    for (int rp = 0; rp < 8; rp++)
        #pragma unroll
        for (int j = 0; j < 4; j++) acc[rp][j] = 0ull;

    for (int c = 0; c < NCH; c++) {
        int buf = c & 1;
        bool havenext = (c + 1 < NCH);
        if (havenext) {
            int k0 = (c + 1) * 16;
            const float* wsrc = (k0 < KIN) ? (selfW + (size_t)k0 * 128)
                                           : (dW + (size_t)(k0 - KIN) * 128);
            #pragma unroll
            for (int q = 0; q < 2; q++) {
                a[q] = rvalid ? *(const float4*)(Grow + k0 + 4 * q) : make_float4(0,0,0,0);
                w[q] = ((const float4*)wsrc)[tid + q * 256];
            }
        }
        compute_chunk(As2[buf], Ws2[buf], tx, ty, acc);
        if (havenext) sts_chunk(As2[buf ^ 1], Ws2[buf ^ 1], tid, a, w);
        __syncthreads();
    }

    // epilogue: bias, store, BN partials
    float psum[4], psq[4];
    #pragma unroll
    for (int j = 0; j < 4; j++) { psum[j] = 0.f; psq[j] = 0.f; }
    #pragma unroll
    for (int rp = 0; rp < 8; rp++) {
        float xe[4], xo[4];
        #pragma unroll
        for (int j = 0; j < 4; j++) {
            unpack2(acc[rp][j], xe[j], xo[j]);
        }
        xe[0] += bcol.x; xe[1] += bcol.y; xe[2] += bcol.z; xe[3] += bcol.w;
        xo[0] += bcol.x; xo[1] += bcol.y; xo[2] += bcol.z; xo[3] += bcol.w;
        int re = rowbase + ty * 16 + 2 * rp;
        if (re < rowend) {
            *(float4*)(Xout + (size_t)re * 128 + tx * 4) =
                make_float4(xe[0], xe[1], xe[2], xe[3]);
            #pragma unroll
            for (int j = 0; j < 4; j++) { psum[j] += xe[j]; psq[j] += xe[j] * xe[j]; }
        }
        if (re + 1 < rowend) {
            *(float4*)(Xout + (size_t)(re + 1) * 128 + tx * 4) =
                make_float4(xo[0], xo[1], xo[2], xo[3]);
            #pragma unroll
            for (int j = 0; j < 4; j++) { psum[j] += xo[j]; psq[j] += xo[j] * xo[j]; }
        }
    }
    float* redS = &As2[0][0];      // 8*128 floats
    float* redQ = redS + 1024;
    #pragma unroll
    for (int j = 0; j < 4; j++) {
        redS[ty * 128 + tx * 4 + j] = psum[j];
        redQ[ty * 128 + tx * 4 + j] = psq[j];
    }
    __syncthreads();
    if (tid < 128) {
        float s = 0.f, q = 0.f;
        #pragma unroll
        for (int t = 0; t < 8; t++) { s += redS[t * 128 + tid]; q += redQ[t * 128 + tid]; }
        atomicAdd(&g_stats[statsOff + tid], s);
        atomicAdd(&g_stats[statsOff + 128 + tid], q);
    }
}

// ---------------- fp update ----------------
template <int KIN, bool NORM>
__global__ __launch_bounds__(256, 2)
void fp_kernel(const float* __restrict__ Hin,
               const float* __restrict__ W, const float* __restrict__ bias,
               const int* __restrict__ mol_ids,
               float* __restrict__ fp, int scOff) {
    constexpr int NCH = KIN / 16;
    __shared__ alignas(16) float As2[2][16 * ARS];
    __shared__ alignas(16) float Ws2[2][16 * ARS];
    __shared__ float sc_s[128], sh_s[128];

    int tid = threadIdx.x;
    int tx = tid & 31, ty = tid >> 5;
    int rowbase = blockIdx.x * 128;

    int rl = tid & 127, kk = (tid >> 7) * 8;
    int rg = rowbase + rl;
    bool rvalid = rg < NA;
    const float* Hrow = Hin + (size_t)rg * KIN + kk;

    float4 bcol = *(const float4*)&bias[tx * 4];

    if (NORM) {
        if (tid < KIN) { sc_s[tid] = g_sc[scOff + tid]; sh_s[tid] = g_sh[scOff + tid]; }
        __syncthreads();
    }

    auto bn4 = [&](float4& v, int c) {
        if (NORM) {
            float4 s4 = *(const float4*)&sc_s[c];
            float4 h4 = *(const float4*)&sh_s[c];
            v.x = fmaxf(0.f, fmaf(v.x, s4.x, h4.x));
            v.y = fmaxf(0.f, fmaf(v.y, s4.y, h4.y));
            v.z = fmaxf(0.f, fmaf(v.z, s4.z, h4.z));
            v.w = fmaxf(0.f, fmaf(v.w, s4.w, h4.w));
        }
    };

    float4 a[2], w[2];
    #pragma unroll
    for (int q = 0; q < 2; q++) {
        a[q] = rvalid ? *(const float4*)(Hrow + 4 * q) : make_float4(0,0,0,0);
        bn4(a[q], kk + 4 * q);
        w[q] = ((const float4*)W)[tid + q * 256];
    }
    sts_chunk(As2[0], Ws2[0], tid, a, w);
    __syncthreads();

    u64 acc[8][4];
    #pragma unroll
    for (int rp = 0; rp < 8; rp++)
        #pragma unroll
        for (int j = 0; j < 4; j++) acc[rp][j] = 0ull;

    for (int c = 0; c < NCH; c++) {
        int buf = c & 1;
        bool havenext = (c + 1 < NCH);
        if (havenext) {
            int k0 = (c + 1) * 16;
            const float* wsrc = W + (size_t)k0 * 128;
            #pragma unroll
            for (int q = 0; q < 2; q++) {
                a[q] = rvalid ? *(const float4*)(Hrow + k0 + 4 * q) : make_float4(0,0,0,0);
                bn4(a[q], k0 + kk + 4 * q);
                w[q] = ((const float4*)wsrc)[tid + q * 256];
            }
        }
        compute_chunk(As2[buf], Ws2[buf], tx, ty, acc);
        if (havenext) sts_chunk(As2[buf ^ 1], Ws2[buf ^ 1], tid, a, w);
        __syncthreads();
    }

    int mm[16];
    #pragma unroll
    for (int i = 0; i < 16; i++) {
        int r = rowbase + ty * 16 + i;
        mm[i] = (r < NA) ? mol_ids[r] : -1;
    }

    int cur = -1;
    float run[4];
    #pragma unroll
    for (int rp = 0; rp < 8; rp++) {
        float xr[2][4];
        #pragma unroll
        for (int j = 0; j < 4; j++) {
            unpack2(acc[rp][j], xr[0][j], xr[1][j]);
        }
        xr[0][0] += bcol.x; xr[0][1] += bcol.y; xr[0][2] += bcol.z; xr[0][3] += bcol.w;
        xr[1][0] += bcol.x; xr[1][1] += bcol.y; xr[1][2] += bcol.z; xr[1][3] += bcol.w;
        #pragma unroll
        for (int h = 0; h < 2; h++) {
            float* x = xr[h];
            // softmax across 128 cols: 4 local + full-warp butterfly
            float mx = fmaxf(fmaxf(x[0], x[1]), fmaxf(x[2], x[3]));
            #pragma unroll
            for (int o = 1; o < 32; o <<= 1) mx = fmaxf(mx, __shfl_xor_sync(0xffffffffu, mx, o));
            float s = 0.f;
            #pragma unroll
            for (int j = 0; j < 4; j++) { x[j] = __expf(x[j] - mx); s += x[j]; }
            #pragma unroll
            for (int o = 1; o < 32; o <<= 1) s += __shfl_xor_sync(0xffffffffu, s, o);
            float inv = 1.0f / s;
            #pragma unroll
            for (int j = 0; j < 4; j++) x[j] *= inv;

            int i = 2 * rp + h;
            if (mm[i] >= 0) {
                if (mm[i] != cur) {
                    if (cur >= 0) {
                        #pragma unroll
                        for (int j = 0; j < 4; j++)
                            atomicAdd(&fp[(size_t)cur * 128 + tx * 4 + j], run[j]);
                    }
                    cur = mm[i];
                    #pragma unroll
                    for (int j = 0; j < 4; j++) run[j] = x[j];
                } else {
                    #pragma unroll
                    for (int j = 0; j < 4; j++) run[j] += x[j];
                }
            }
        }
    }
    if (cur >= 0) {
        #pragma unroll
        for (int j = 0; j < 4; j++)
            atomicAdd(&fp[(size_t)cur * 128 + tx * 4 + j], run[j]);
    }
}

// ---------------- launch ----------------
extern "C" void kernel_launch(void* const* d_in, const int* in_sizes, int n_in,
                              void* d_out, int out_size) {
    const float *atom, *bond, *W0, *b0, *W1, *b1, *W2, *b2;
    const float *c1sW, *c1b, *c1d1, *c1d2, *c1d3, *c1d4;
    const float *c2sW, *c2b, *c2d1, *c2d2, *c2d3, *c2d4;
    const int *a1, *a2, *a3, *a4, *e1, *e2, *e3, *e4, *mol;

    if (in_sizes[0] == 12800000) {
        atom = (const float*)d_in[0];
        bond = (const float*)d_in[1];
        if (in_sizes[2] == 8192) {
            W0 = (const float*)d_in[2];  b0 = (const float*)d_in[3];
            W1 = (const float*)d_in[4];  b1 = (const float*)d_in[5];
            W2 = (const float*)d_in[6];  b2 = (const float*)d_in[7];
            c1sW = (const float*)d_in[8];  c1b = (const float*)d_in[9];
            c1d1 = (const float*)d_in[10]; c1d2 = (const float*)d_in[11];
            c1d3 = (const float*)d_in[12]; c1d4 = (const float*)d_in[13];
            c2sW = (const float*)d_in[14]; c2b = (const float*)d_in[15];
            c2d1 = (const float*)d_in[16]; c2d2 = (const float*)d_in[17];
            c2d3 = (const float*)d_in[18]; c2d4 = (const float*)d_in[19];
            a1 = (const int*)d_in[20]; a2 = (const int*)d_in[21];
            a3 = (const int*)d_in[22]; a4 = (const int*)d_in[23];
            e1 = (const int*)d_in[24]; e2 = (const int*)d_in[25];
            e3 = (const int*)d_in[26]; e4 = (const int*)d_in[27];
            mol = (const int*)d_in[28];
        } else if (in_sizes[3] == 50000) {
            a1 = (const int*)d_in[2];  e1 = (const int*)d_in[3];
            a2 = (const int*)d_in[4];  e2 = (const int*)d_in[5];
            a3 = (const int*)d_in[6];  e3 = (const int*)d_in[7];
            a4 = (const int*)d_in[8];  e4 = (const int*)d_in[9];
            mol = (const int*)d_in[10];
            W0 = (const float*)d_in[11]; b0 = (const float*)d_in[12];
            W1 = (const float*)d_in[13]; b1 = (const float*)d_in[14];
            W2 = (const float*)d_in[15]; b2 = (const float*)d_in[16];
            c1sW = (const float*)d_in[17]; c1b = (const float*)d_in[18];
            c1d1 = (const float*)d_in[19]; c1d2 = (const float*)d_in[20];
            c1d3 = (const float*)d_in[21]; c1d4 = (const float*)d_in[22];
            c2sW = (const float*)d_in[23]; c2b = (const float*)d_in[24];
            c2d1 = (const float*)d_in[25]; c2d2 = (const float*)d_in[26];
            c2d3 = (const float*)d_in[27]; c2d4 = (const float*)d_in[28];
        } else {
            a1 = (const int*)d_in[2];  a2 = (const int*)d_in[3];
            a3 = (const int*)d_in[4];  a4 = (const int*)d_in[5];
            e1 = (const int*)d_in[6];  e2 = (const int*)d_in[7];
            e3 = (const int*)d_in[8];  e4 = (const int*)d_in[9];
            mol = (const int*)d_in[10];
            W0 = (const float*)d_in[11]; b0 = (const float*)d_in[12];
            W1 = (const float*)d_in[13]; b1 = (const float*)d_in[14];
            W2 = (const float*)d_in[15]; b2 = (const float*)d_in[16];
            c1sW = (const float*)d_in[17]; c1b = (const float*)d_in[18];
            c1d1 = (const float*)d_in[19]; c1d2 = (const float*)d_in[20];
            c1d3 = (const float*)d_in[21]; c1d4 = (const float*)d_in[22];
            c2sW = (const float*)d_in[23]; c2b = (const float*)d_in[24];
            c2d1 = (const float*)d_in[25]; c2d2 = (const float*)d_in[26];
            c2d3 = (const float*)d_in[27]; c2d4 = (const float*)d_in[28];
        }
    } else {
        a1 = (const int*)d_in[0];  a2 = (const int*)d_in[1];
        a3 = (const int*)d_in[2];  a4 = (const int*)d_in[3];
        atom = (const float*)d_in[4];
        e1 = (const int*)d_in[5];  e2 = (const int*)d_in[6];
        e3 = (const int*)d_in[7];  e4 = (const int*)d_in[8];
        bond = (const float*)d_in[9];
        c1b = (const float*)d_in[10];
        c1d1 = (const float*)d_in[11]; c1d2 = (const float*)d_in[12];
        c1d3 = (const float*)d_in[13]; c1d4 = (const float*)d_in[14];
        c1sW = (const float*)d_in[15];
        c2b = (const float*)d_in[16];
        c2d1 = (const float*)d_in[17]; c2d2 = (const float*)d_in[18];
        c2d3 = (const float*)d_in[19]; c2d4 = (const float*)d_in[20];
        c2sW = (const float*)d_in[21];
        mol = (const int*)d_in[22];
        if (in_sizes[24] == 128) {
            W0 = (const float*)d_in[23]; b0 = (const float*)d_in[24];
            W1 = (const float*)d_in[25]; b1 = (const float*)d_in[26];
            W2 = (const float*)d_in[27]; b2 = (const float*)d_in[28];
        } else {
            W0 = (const float*)d_in[23]; W1 = (const float*)d_in[24];
            W2 = (const float*)d_in[25];
            b0 = (const float*)d_in[26]; b1 = (const float*)d_in[27];
            b2 = (const float*)d_in[28];
        }
    }

    float* fp = (float*)d_out;

    float *Hp, *Xp;
    cudaGetSymbolAddress((void**)&Hp, g_H);
    cudaGetSymbolAddress((void**)&Xp, g_X);

    cudaMemsetAsync(d_out, 0, (size_t)out_size * sizeof(float));
    zero_stats_kernel<<<1, 512>>>();

    // fp += segsum(softmax(atom @ W0 + b0))
    fp_kernel<64, false><<<FPB, 256>>>(atom, W0, b0, mol, fp, 0);

    // layer 1: gather (raw atom), conv -> g_H (pre-BN) + stats, prep BN consts
    {
        long long total = (long long)NA * 36;
        int gblocks = (int)((total + 255) / 256);
        gather_kernel<64, false><<<gblocks, 256>>>(atom, bond, a1, a2, a3, a4, e1, e2, e3, e4, 0);
    }
    conv_kernel<64><<<4 * TPD, 256>>>(c1sW, c1d1, c1d2, c1d3, c1d4, c1b, Hp, 0);
    prep_stats_kernel<<<1, 128>>>(0, 0);

    // fp += segsum(softmax(bn_relu(H) @ W1 + b1))
    fp_kernel<128, true><<<FPB, 256>>>(Hp, W1, b1, mol, fp, 0);

    // layer 2: gather with fused BN+relu on H, conv -> g_X + stats, prep BN consts
    {
        long long total = (long long)NA * 68;
        int gblocks = (int)((total + 255) / 256);
        gather_kernel<128, true><<<gblocks, 256>>>(Hp, bond, a1, a2, a3, a4, e1, e2, e3, e4, 0);
    }
    conv_kernel<128><<<4 * TPD, 256>>>(c2sW, c2d1, c2d2, c2d3, c2d4, c2b, Xp, 256);
    prep_stats_kernel<<<1, 128>>>(256, 128);

    // fp += segsum(softmax(bn_relu(X) @ W2 + b2))
    fp_kernel<128, true><<<FPB, 256>>>(Xp, W2, b2, mol, fp, 128);
}